// round 9
// baseline (speedup 1.0000x reference)
#include <cuda_runtime.h>
#include <cuda_bf16.h>

// out = x + total, total = n*(n-1)/2 if n>1 else 0, n = trunc(sum(x)),
// x: 8192x8192 fp32 (64M elems, 256MB).
//
// R8 post-mortem applied:
//  - the non-persistent contiguous-window shape won the add (6.27 TB/s).
//    Now the reduce gets the same shape: 2048 blocks, each a contiguous
//    128KB chunk, 32 float4/thread with MLP=4 front-batched loads.
//  - chunk mapping is REVERSED (block b -> chunk 2047-b): early CTAs eat the
//    tail, late CTAs the front -> L2 ends holding x's front, which the add's
//    first wave reads.
//  - last-block fused finalize kept (atomic arrival counter, reset by the
//    finisher; fixed-order final sum -> deterministic every replay).
//  - add unchanged: one float4/thread, __ldcs/__stcs.

#define NTHREADS 256
#define RED_BLOCKS 2048
#define CHUNK 8192          // float4 elements per block (128 KB)

__device__ double g_partials[RED_BLOCKS];
__device__ float g_total;
__device__ unsigned int g_arrive;   // zero-init; finisher resets each launch

__global__ __launch_bounds__(NTHREADS)
void reduce_kernel(const float4* __restrict__ x4, long long n4) {
    // reversed chunk mapping for L2 carryover
    const int cb = (RED_BLOCKS - 1) - (int)blockIdx.x;
    const long long base = (long long)cb * CHUNK + threadIdx.x;

    float a0 = 0.f, a1 = 0.f, a2 = 0.f, a3 = 0.f;
    if ((long long)(cb + 1) * CHUNK <= n4) {
        // full chunk fast path: 32 float4/thread, 4 independent loads in flight
        #pragma unroll
        for (int k = 0; k < CHUNK / NTHREADS; k += 4) {
            float4 v0 = x4[base + (long long)(k + 0) * NTHREADS];
            float4 v1 = x4[base + (long long)(k + 1) * NTHREADS];
            float4 v2 = x4[base + (long long)(k + 2) * NTHREADS];
            float4 v3 = x4[base + (long long)(k + 3) * NTHREADS];
            a0 += v0.x; a1 += v0.y; a2 += v0.z; a3 += v0.w;
            a0 += v1.x; a1 += v1.y; a2 += v1.z; a3 += v1.w;
            a0 += v2.x; a1 += v2.y; a2 += v2.z; a3 += v2.w;
            a0 += v3.x; a1 += v3.y; a2 += v3.z; a3 += v3.w;
        }
    } else {
        for (int k = 0; k < CHUNK / NTHREADS; k++) {
            long long i = base + (long long)k * NTHREADS;
            if (i < n4) {
                float4 v = x4[i];
                a0 += v.x; a1 += v.y; a2 += v.z; a3 += v.w;
            }
        }
    }
    double acc = ((double)a0 + (double)a1) + ((double)a2 + (double)a3);

    __shared__ double s[NTHREADS];
    s[threadIdx.x] = acc;
    __syncthreads();
    #pragma unroll
    for (int off = NTHREADS / 2; off > 0; off >>= 1) {
        if (threadIdx.x < off) s[threadIdx.x] += s[threadIdx.x + off];
        __syncthreads();
    }

    __shared__ int is_last;
    if (threadIdx.x == 0) {
        g_partials[cb] = s[0];                 // indexed by chunk: fixed order
        __threadfence();                       // partial visible GPU-wide
        unsigned int prev = atomicAdd(&g_arrive, 1u);
        is_last = (prev == RED_BLOCKS - 1);
        if (is_last) atomicExch(&g_arrive, 0u);  // reset for next graph replay
    }
    __syncthreads();

    // Last-arriving CTA finalizes in a FIXED order -> deterministic result
    // regardless of which CTA is last.
    if (is_last) {
        double acc2 = 0.0;
        #pragma unroll
        for (int i = threadIdx.x; i < RED_BLOCKS; i += NTHREADS)
            acc2 += g_partials[i];
        s[threadIdx.x] = acc2;
        __syncthreads();
        #pragma unroll
        for (int off = NTHREADS / 2; off > 0; off >>= 1) {
            if (threadIdx.x < off) s[threadIdx.x] += s[threadIdx.x + off];
            __syncthreads();
        }
        if (threadIdx.x == 0) {
            double total_sum = s[0];
            double nn = trunc(total_sum);   // int() truncates toward zero
            g_total = (float)((nn > 1.0) ? nn * (nn - 1.0) * 0.5 : 0.0);
        }
    }
}

// Non-persistent streaming add: one float4 per thread, contiguous concurrent
// address window -> best DRAM page locality for the mixed r/w stream.
__global__ __launch_bounds__(NTHREADS)
void add_kernel(const float4* __restrict__ x4, float4* __restrict__ o4,
                long long n4) {
    const float t = g_total;
    long long i = (long long)blockIdx.x * NTHREADS + threadIdx.x;
    if (i < n4) {
        float4 v = __ldcs(&x4[i]);
        v.x += t; v.y += t; v.z += t; v.w += t;
        __stcs(&o4[i], v);
    }
}

extern "C" void kernel_launch(void* const* d_in, const int* in_sizes, int n_in,
                              void* d_out, int out_size) {
    const float* x = (const float*)d_in[0];
    float* out = (float*)d_out;
    long long n = (long long)in_sizes[0];     // 67108864, divisible by 4
    long long n4 = n / 4;                     // 16777216 = 2048 * 8192 exactly

    reduce_kernel<<<RED_BLOCKS, NTHREADS>>>((const float4*)x, n4);
    long long add_blocks = (n4 + NTHREADS - 1) / NTHREADS;
    add_kernel<<<(unsigned)add_blocks, NTHREADS>>>((const float4*)x,
                                                   (float4*)out, n4);
}

// round 10
// speedup vs baseline: 1.0463x; 1.0463x over previous
#include <cuda_runtime.h>
#include <cuda_bf16.h>

// out = x + total, total = n*(n-1)/2 if n>1 else 0, n = trunc(sum(x)),
// x: 8192x8192 fp32 (64M elems, 256MB).
//
// R9 post-mortem: contiguous-chunk reduce REVERTED (slower than persistent
// grid-stride for the pure-read stream). Base = R8 (125.0us best).
// R10 adds:
//  - PDL: the add launches with programmaticStreamSerialization and issues
//    its x-loads BEFORE cudaGridDependencySynchronize(), overlapping the
//    reduce's tail; g_total is read only after the sync. No trigger in the
//    reduce -> sync waits for primary exit -> always correct.
//  - add: 2 float4/thread (front-batched, contiguous window kept).

#define NTHREADS 256
#define RED_BLOCKS 740      // 148 SMs * 5 CTAs — one exact wave

__device__ double g_partials[RED_BLOCKS];
__device__ float g_total;
__device__ unsigned int g_arrive;   // zero-init; finisher resets each launch

__global__ __launch_bounds__(NTHREADS, 5)
void reduce_kernel(const float4* __restrict__ x4, long long n4) {
    float a0 = 0.f, a1 = 0.f, a2 = 0.f, a3 = 0.f;
    const long long stride = (long long)RED_BLOCKS * NTHREADS;
    const long long tid = (long long)blockIdx.x * NTHREADS + threadIdx.x;
    const long long niter = (n4 + stride - 1) / stride;

    long long j = niter - 1;
    // top (possibly partial) chunk; walk BACKWARD so L2 ends holding x's front
    {
        long long i = j * stride + tid;
        if (i < n4) {
            float4 v = x4[i];
            a0 += v.x; a1 += v.y; a2 += v.z; a3 += v.w;
        }
        j--;
    }
    for (; j >= 3; j -= 4) {
        float4 v0 = x4[(j    ) * stride + tid];
        float4 v1 = x4[(j - 1) * stride + tid];
        float4 v2 = x4[(j - 2) * stride + tid];
        float4 v3 = x4[(j - 3) * stride + tid];
        a0 += v0.x; a1 += v0.y; a2 += v0.z; a3 += v0.w;
        a0 += v1.x; a1 += v1.y; a2 += v1.z; a3 += v1.w;
        a0 += v2.x; a1 += v2.y; a2 += v2.z; a3 += v2.w;
        a0 += v3.x; a1 += v3.y; a2 += v3.z; a3 += v3.w;
    }
    for (; j >= 0; j--) {
        float4 v = x4[j * stride + tid];
        a0 += v.x; a1 += v.y; a2 += v.z; a3 += v.w;
    }
    double acc = ((double)a0 + (double)a1) + ((double)a2 + (double)a3);

    __shared__ double s[NTHREADS];
    s[threadIdx.x] = acc;
    __syncthreads();
    #pragma unroll
    for (int off = NTHREADS / 2; off > 0; off >>= 1) {
        if (threadIdx.x < off) s[threadIdx.x] += s[threadIdx.x + off];
        __syncthreads();
    }

    __shared__ int is_last;
    if (threadIdx.x == 0) {
        g_partials[blockIdx.x] = s[0];
        __threadfence();                       // partial visible GPU-wide
        unsigned int prev = atomicAdd(&g_arrive, 1u);
        is_last = (prev == RED_BLOCKS - 1);
        if (is_last) atomicExch(&g_arrive, 0u);  // reset for next graph replay
    }
    __syncthreads();

    // Last-arriving CTA finalizes in a FIXED order -> deterministic result
    // regardless of which CTA is last.
    if (is_last) {
        double acc2 = 0.0;
        #pragma unroll
        for (int i = threadIdx.x; i < RED_BLOCKS; i += NTHREADS)
            acc2 += g_partials[i];
        s[threadIdx.x] = acc2;
        __syncthreads();
        #pragma unroll
        for (int off = NTHREADS / 2; off > 0; off >>= 1) {
            if (threadIdx.x < off) s[threadIdx.x] += s[threadIdx.x + off];
            __syncthreads();
        }
        if (threadIdx.x == 0) {
            double total_sum = s[0];
            double nn = trunc(total_sum);   // int() truncates toward zero
            g_total = (float)((nn > 1.0) ? nn * (nn - 1.0) * 0.5 : 0.0);
        }
    }
}

// Non-persistent streaming add, 2 float4/thread, PDL-overlapped:
// loads issue before the grid-dependency sync (read-only, no hazard),
// g_total is read after it.
__global__ __launch_bounds__(NTHREADS)
void add_kernel(const float4* __restrict__ x4, float4* __restrict__ o4,
                long long n4) {
    const long long base = (long long)blockIdx.x * (2 * NTHREADS) + threadIdx.x;
    const long long i0 = base;
    const long long i1 = base + NTHREADS;

    float4 v0, v1;
    bool p0 = i0 < n4, p1 = i1 < n4;
    if (p0) v0 = __ldcs(&x4[i0]);
    if (p1) v1 = __ldcs(&x4[i1]);

    cudaGridDependencySynchronize();   // wait for reduce grid to finish

    const float t = g_total;
    if (p0) {
        v0.x += t; v0.y += t; v0.z += t; v0.w += t;
        __stcs(&o4[i0], v0);
    }
    if (p1) {
        v1.x += t; v1.y += t; v1.z += t; v1.w += t;
        __stcs(&o4[i1], v1);
    }
}

extern "C" void kernel_launch(void* const* d_in, const int* in_sizes, int n_in,
                              void* d_out, int out_size) {
    const float* x = (const float*)d_in[0];
    float* out = (float*)d_out;
    long long n = (long long)in_sizes[0];     // 67108864, divisible by 4
    long long n4 = n / 4;                     // 16777216

    reduce_kernel<<<RED_BLOCKS, NTHREADS>>>((const float4*)x, n4);

    long long add_blocks = (n4 + 2 * NTHREADS - 1) / (2 * NTHREADS);  // 32768

    cudaLaunchConfig_t cfg = {};
    cfg.gridDim = dim3((unsigned)add_blocks, 1, 1);
    cfg.blockDim = dim3(NTHREADS, 1, 1);
    cfg.dynamicSmemBytes = 0;
    cfg.stream = 0;
    cudaLaunchAttribute attr[1];
    attr[0].id = cudaLaunchAttributeProgrammaticStreamSerialization;
    attr[0].val.programmaticStreamSerializationAllowed = 1;
    cfg.attrs = attr;
    cfg.numAttrs = 1;
    cudaLaunchKernelEx(&cfg, add_kernel, (const float4*)x, (float4*)out, n4);
}

// round 11
// speedup vs baseline: 1.0465x; 1.0003x over previous
#include <cuda_runtime.h>
#include <cuda_bf16.h>

// out = x + total, total = n*(n-1)/2 if n>1 else 0, n = trunc(sum(x)),
// x: 8192x8192 fp32 (64M elems, 256MB).
//
// R10 post-mortem applied:
//  - reduce is the laggard (5.7 TB/s vs add's 6.8 effective). More DRAM
//    concurrency: MLP=8 front-batched loads, clamp 4 (592 blocks = 148*4,
//    one exact wave, 64-reg budget).
//  - add: 4 float4/thread (16KB contiguous window), all 4 loads issued
//    BEFORE cudaGridDependencySynchronize() for deeper PDL overlap.
//  - kept: backward reduce walk, last-block fused deterministic finalize,
//    __ldcs/__stcs streaming on the add.

#define NTHREADS 256
#define RED_BLOCKS 592      // 148 SMs * 4 CTAs — one exact wave

__device__ double g_partials[RED_BLOCKS];
__device__ float g_total;
__device__ unsigned int g_arrive;   // zero-init; finisher resets each launch

__global__ __launch_bounds__(NTHREADS, 4)
void reduce_kernel(const float4* __restrict__ x4, long long n4) {
    float a0 = 0.f, a1 = 0.f, a2 = 0.f, a3 = 0.f;
    const long long stride = (long long)RED_BLOCKS * NTHREADS;
    const long long tid = (long long)blockIdx.x * NTHREADS + threadIdx.x;
    const long long niter = (n4 + stride - 1) / stride;

    long long j = niter - 1;
    // top (possibly partial) chunk; walk BACKWARD so L2 ends holding x's front
    {
        long long i = j * stride + tid;
        if (i < n4) {
            float4 v = x4[i];
            a0 += v.x; a1 += v.y; a2 += v.z; a3 += v.w;
        }
        j--;
    }
    // MLP=8 main loop: 8 independent loads in flight
    for (; j >= 7; j -= 8) {
        float4 v0 = x4[(j    ) * stride + tid];
        float4 v1 = x4[(j - 1) * stride + tid];
        float4 v2 = x4[(j - 2) * stride + tid];
        float4 v3 = x4[(j - 3) * stride + tid];
        float4 v4 = x4[(j - 4) * stride + tid];
        float4 v5 = x4[(j - 5) * stride + tid];
        float4 v6 = x4[(j - 6) * stride + tid];
        float4 v7 = x4[(j - 7) * stride + tid];
        a0 += v0.x; a1 += v0.y; a2 += v0.z; a3 += v0.w;
        a0 += v1.x; a1 += v1.y; a2 += v1.z; a3 += v1.w;
        a0 += v2.x; a1 += v2.y; a2 += v2.z; a3 += v2.w;
        a0 += v3.x; a1 += v3.y; a2 += v3.z; a3 += v3.w;
        a0 += v4.x; a1 += v4.y; a2 += v4.z; a3 += v4.w;
        a0 += v5.x; a1 += v5.y; a2 += v5.z; a3 += v5.w;
        a0 += v6.x; a1 += v6.y; a2 += v6.z; a3 += v6.w;
        a0 += v7.x; a1 += v7.y; a2 += v7.z; a3 += v7.w;
    }
    for (; j >= 0; j--) {
        float4 v = x4[j * stride + tid];
        a0 += v.x; a1 += v.y; a2 += v.z; a3 += v.w;
    }
    double acc = ((double)a0 + (double)a1) + ((double)a2 + (double)a3);

    __shared__ double s[NTHREADS];
    s[threadIdx.x] = acc;
    __syncthreads();
    #pragma unroll
    for (int off = NTHREADS / 2; off > 0; off >>= 1) {
        if (threadIdx.x < off) s[threadIdx.x] += s[threadIdx.x + off];
        __syncthreads();
    }

    __shared__ int is_last;
    if (threadIdx.x == 0) {
        g_partials[blockIdx.x] = s[0];
        __threadfence();                       // partial visible GPU-wide
        unsigned int prev = atomicAdd(&g_arrive, 1u);
        is_last = (prev == RED_BLOCKS - 1);
        if (is_last) atomicExch(&g_arrive, 0u);  // reset for next graph replay
    }
    __syncthreads();

    // Last-arriving CTA finalizes in a FIXED order -> deterministic result
    // regardless of which CTA is last.
    if (is_last) {
        double acc2 = 0.0;
        #pragma unroll
        for (int i = threadIdx.x; i < RED_BLOCKS; i += NTHREADS)
            acc2 += g_partials[i];
        s[threadIdx.x] = acc2;
        __syncthreads();
        #pragma unroll
        for (int off = NTHREADS / 2; off > 0; off >>= 1) {
            if (threadIdx.x < off) s[threadIdx.x] += s[threadIdx.x + off];
            __syncthreads();
        }
        if (threadIdx.x == 0) {
            double total_sum = s[0];
            double nn = trunc(total_sum);   // int() truncates toward zero
            g_total = (float)((nn > 1.0) ? nn * (nn - 1.0) * 0.5 : 0.0);
        }
    }
}

// Non-persistent streaming add, 4 float4/thread, PDL-overlapped:
// all loads issue before the grid-dependency sync (read-only, no hazard),
// g_total is read after it.
__global__ __launch_bounds__(NTHREADS)
void add_kernel(const float4* __restrict__ x4, float4* __restrict__ o4,
                long long n4) {
    const long long base = (long long)blockIdx.x * (4 * NTHREADS) + threadIdx.x;
    const long long i0 = base;
    const long long i1 = base + NTHREADS;
    const long long i2 = base + 2 * NTHREADS;
    const long long i3 = base + 3 * NTHREADS;

    float4 v0, v1, v2, v3;
    bool p0 = i0 < n4, p1 = i1 < n4, p2 = i2 < n4, p3 = i3 < n4;
    if (p0) v0 = __ldcs(&x4[i0]);
    if (p1) v1 = __ldcs(&x4[i1]);
    if (p2) v2 = __ldcs(&x4[i2]);
    if (p3) v3 = __ldcs(&x4[i3]);

    cudaGridDependencySynchronize();   // wait for reduce grid to finish

    const float t = g_total;
    if (p0) { v0.x += t; v0.y += t; v0.z += t; v0.w += t; __stcs(&o4[i0], v0); }
    if (p1) { v1.x += t; v1.y += t; v1.z += t; v1.w += t; __stcs(&o4[i1], v1); }
    if (p2) { v2.x += t; v2.y += t; v2.z += t; v2.w += t; __stcs(&o4[i2], v2); }
    if (p3) { v3.x += t; v3.y += t; v3.z += t; v3.w += t; __stcs(&o4[i3], v3); }
}

extern "C" void kernel_launch(void* const* d_in, const int* in_sizes, int n_in,
                              void* d_out, int out_size) {
    const float* x = (const float*)d_in[0];
    float* out = (float*)d_out;
    long long n = (long long)in_sizes[0];     // 67108864, divisible by 4
    long long n4 = n / 4;                     // 16777216

    reduce_kernel<<<RED_BLOCKS, NTHREADS>>>((const float4*)x, n4);

    long long add_blocks = (n4 + 4 * NTHREADS - 1) / (4 * NTHREADS);  // 16384

    cudaLaunchConfig_t cfg = {};
    cfg.gridDim = dim3((unsigned)add_blocks, 1, 1);
    cfg.blockDim = dim3(NTHREADS, 1, 1);
    cfg.dynamicSmemBytes = 0;
    cfg.stream = 0;
    cudaLaunchAttribute attr[1];
    attr[0].id = cudaLaunchAttributeProgrammaticStreamSerialization;
    attr[0].val.programmaticStreamSerializationAllowed = 1;
    cfg.attrs = attr;
    cfg.numAttrs = 1;
    cudaLaunchKernelEx(&cfg, add_kernel, (const float4*)x, (float4*)out, n4);
}